// round 9
// baseline (speedup 1.0000x reference)
#include <cuda_runtime.h>
#include <cuda_bf16.h>
#include <cuda_fp16.h>
#include <cstdint>

// Problem constants (match reference)
#define NN 50000
#define EE 800000
#define DD 128

// ---------------- device scratch (no allocations allowed) ----------------
__device__ float g_hs[NN * DD];                 // h * norm_src (layer-1 messages, fp32)
__device__ __half g_mh0[NN * DD];               // fp16 messages ping
__device__ __half g_mh1[NN * DD];               // fp16 messages pong
__device__ __nv_bfloat16 g_wthi[3 * DD * DD];   // W^T split-hi, [layer][n][k]
__device__ __nv_bfloat16 g_wtlo[3 * DD * DD];   // W^T split-lo
__device__ float g_norm_src[NN];
__device__ float g_norm_dst[NN];
__device__ int   g_deg_out[NN];
__device__ int   g_deg_in[NN];
__device__ int   g_ptr[NN + 1];      // CSR row pointers (by dst)
__device__ int   g_cur[NN];          // scatter cursors
__device__ int   g_col[EE];          // CSR column indices (src node ids)
__device__ int   g_bsum[1024];       // per-block partial sums for scan

// ---------------- tiny setup kernels ----------------
__global__ void k_zero_degs(int n) {
    int i = blockIdx.x * blockDim.x + threadIdx.x;
    if (i < n) { g_deg_out[i] = 0; g_deg_in[i] = 0; }
}

__global__ void k_count(const int* __restrict__ src, const int* __restrict__ dst, int e) {
    int i = blockIdx.x * blockDim.x + threadIdx.x;
    if (i < e) {
        atomicAdd(&g_deg_out[src[i]], 1);
        atomicAdd(&g_deg_in[dst[i]], 1);
    }
}

// Fused: norms + per-block exclusive scan of deg_in (local) + block total.
__global__ void k_norms_scan1(int n) {
    __shared__ int wsum[8];
    int i = blockIdx.x * blockDim.x + threadIdx.x;
    int t = threadIdx.x;
    int lane = t & 31;
    int w = t >> 5;

    int din = 0;
    if (i < n) {
        int dout = g_deg_out[i];
        din = g_deg_in[i];
        g_norm_src[i] = rsqrtf((float)max(dout, 1));
        g_norm_dst[i] = rsqrtf((float)max(din, 1));
    }
    int v = din;
    #pragma unroll
    for (int off = 1; off < 32; off <<= 1) {
        int y = __shfl_up_sync(0xFFFFFFFFu, v, off);
        if (lane >= off) v += y;
    }
    if (lane == 31) wsum[w] = v;
    __syncthreads();
    if (t < 8) {
        int sv = wsum[t];
        #pragma unroll
        for (int off = 1; off < 8; off <<= 1) {
            int y = __shfl_up_sync(0xFFu, sv, off);
            if (t >= off) sv += y;
        }
        wsum[t] = sv;
    }
    __syncthreads();
    int warp_prefix = (w > 0) ? wsum[w - 1] : 0;
    int excl = v - din + warp_prefix;
    if (i < n) g_ptr[i] = excl;
    if (t == 255) g_bsum[blockIdx.x] = excl + din;
}

__global__ void k_scan_bsums(int n, int nb) {
    __shared__ int wsum[8];
    __shared__ int s_carry;
    int t = threadIdx.x;
    int lane = t & 31;
    int w = t >> 5;
    if (t == 0) s_carry = 0;
    __syncthreads();
    for (int base = 0; base < nb; base += 256) {
        int i = base + t;
        int x = (i < nb) ? g_bsum[i] : 0;
        int v = x;
        #pragma unroll
        for (int off = 1; off < 32; off <<= 1) {
            int y = __shfl_up_sync(0xFFFFFFFFu, v, off);
            if (lane >= off) v += y;
        }
        if (lane == 31) wsum[w] = v;
        __syncthreads();
        if (t < 8) {
            int sv = wsum[t];
            #pragma unroll
            for (int off = 1; off < 8; off <<= 1) {
                int y = __shfl_up_sync(0xFFu, sv, off);
                if (t >= off) sv += y;
            }
            wsum[t] = sv;
        }
        __syncthreads();
        int warp_prefix = (w > 0) ? wsum[w - 1] : 0;
        int incl = v + warp_prefix + s_carry;
        if (i < nb) g_bsum[i] = incl - x;
        __syncthreads();
        if (t == 255) s_carry = incl;
        __syncthreads();
    }
    if (t == 0) g_ptr[n] = s_carry;
}

__global__ void k_add_off(int n) {
    int i = blockIdx.x * blockDim.x + threadIdx.x;
    if (i < n) {
        int p = g_ptr[i] + g_bsum[blockIdx.x];
        g_ptr[i] = p;
        g_cur[i] = p;
    }
}

__global__ void k_scatter(const int* __restrict__ src, const int* __restrict__ dst, int e) {
    int i = blockIdx.x * blockDim.x + threadIdx.x;
    if (i < e) {
        int p = atomicAdd(&g_cur[dst[i]], 1);
        g_col[p] = src[i];
    }
}

// embedding gather + pre-scale by norm_src -> g_hs (fp32)
__global__ void k_embed(const int* __restrict__ batch, const float* __restrict__ emb, int n) {
    int i = blockIdx.x * blockDim.x + threadIdx.x;
    if (i < n * 32) {
        int v = i >> 5;
        int c = i & 31;
        int id = __ldg(&batch[v]);
        float4 val = __ldg(((const float4*)emb) + (size_t)id * 32 + c);
        float ns = g_norm_src[v];
        float4 o;
        o.x = val.x * ns;
        o.y = val.y * ns;
        o.z = val.z * ns;
        o.w = val.w * ns;
        ((float4*)g_hs)[(size_t)v * 32 + c] = o;
    }
}

// W^T split prep: 3*128 blocks of 128 thr: block = (layer, k); thread = n.
__global__ void k_wprep(const float* __restrict__ W1, const float* __restrict__ W2,
                        const float* __restrict__ W3) {
    int k = blockIdx.x & 127;
    int layer = blockIdx.x >> 7;
    const float* W = (layer == 0) ? W1 : (layer == 1) ? W2 : W3;
    int nn = threadIdx.x;
    float w = W[k * DD + nn];
    __nv_bfloat16 h = __float2bfloat16_rn(w);
    float l = w - __bfloat162float(h);
    g_wthi[layer * DD * DD + nn * DD + k] = h;
    g_wtlo[layer * DD * DD + nn * DD + k] = __float2bfloat16_rn(l);
}

// ---------------- helpers ----------------
__device__ __forceinline__ unsigned int pack2_hi_lo(float x, float y, float& lx, float& ly) {
    __nv_bfloat16 hx = __float2bfloat16_rn(x);
    __nv_bfloat16 hy = __float2bfloat16_rn(y);
    lx = x - __bfloat162float(hx);
    ly = y - __bfloat162float(hy);
    __nv_bfloat162 p = __halves2bfloat162(hx, hy);
    return *reinterpret_cast<unsigned int*>(&p);
}
__device__ __forceinline__ unsigned int pack2(float x, float y) {
    __nv_bfloat162 p = __floats2bfloat162_rn(x, y);
    return *reinterpret_cast<unsigned int*>(&p);
}

__device__ __forceinline__ void acc_h4(float4& acc, uint2 m) {
    __half2 p0 = *reinterpret_cast<__half2*>(&m.x);
    __half2 p1 = *reinterpret_cast<__half2*>(&m.y);
    float2 f0 = __half22float2(p0);
    float2 f1 = __half22float2(p1);
    acc.x += f0.x;
    acc.y += f0.y;
    acc.z += f1.x;
    acc.w += f1.y;
}

__device__ __forceinline__ void mma_bf16(float* c,
                                         unsigned int a0, unsigned int a1,
                                         unsigned int a2, unsigned int a3,
                                         unsigned int b0, unsigned int b1) {
    asm volatile("mma.sync.aligned.m16n8k16.row.col.f32.bf16.bf16.f32 "
                 "{%0,%1,%2,%3}, {%4,%5,%6,%7}, {%8,%9}, {%0,%1,%2,%3};"
                 : "+f"(c[0]), "+f"(c[1]), "+f"(c[2]), "+f"(c[3])
                 : "r"(a0), "r"(a1), "r"(a2), "r"(a3), "r"(b0), "r"(b1));
}

// ---------------- fused layer kernel: SpMM (pull) + split-bf16 MMA GEMM ----------------
// 256 threads, BM=128 nodes/block. Phase 1: 8 warps x 16 nodes gather+pack into smem A.
// Phase 2: BN=128, K=128 in 2 chunks of 64 (W smem buffer reused).
// A smem: full K, row stride 68 words (64 data + 4 pad). W smem: 64-k chunk, stride 36.
// Input and output message buffers are DISTINCT (ping-pong) — no cross-block aliasing.
#define SROW_A 68
#define SROW_W 36
#define SM_AHI 0
#define SM_ALO (128 * SROW_A)
#define SM_WHI (2 * 128 * SROW_A)
#define SM_WLO (2 * 128 * SROW_A + 128 * SROW_W)
#define FUSED_SMEM ((2 * 128 * SROW_A + 2 * 128 * SROW_W) * 4)

// mode_in: 0 = gather fp32 g_hs, 1 = gather fp16 from min (distinct from mout).
// mode_out: 1 = write fp16 messages to mout, 0 = write fp32 to out.
__global__ void __launch_bounds__(256, 2) k_layer(int layer, const float* __restrict__ b,
                                                  float* __restrict__ out, int n,
                                                  int mode_in, int mode_out,
                                                  const __half* __restrict__ min_buf,
                                                  __half* __restrict__ mout_buf) {
    extern __shared__ unsigned int sm[];
    unsigned int* sAhi = sm + SM_AHI;
    unsigned int* sAlo = sm + SM_ALO;
    unsigned int* sWhi = sm + SM_WHI;
    unsigned int* sWlo = sm + SM_WLO;

    int tid = threadIdx.x;
    int lane = tid & 31;
    int warp = tid >> 5;
    int row0 = blockIdx.x * 128;

    const int4* Whi4 = (const int4*)(g_wthi + layer * DD * DD);
    const int4* Wlo4 = (const int4*)(g_wtlo + layer * DD * DD);

    // ---- load W chunk kc=0 (issued first so it overlaps the gather) ----
    #pragma unroll
    for (int j = 0; j < 4; j++) {
        int idx = tid + j * 256;
        int r = idx >> 3;
        int w16 = idx & 7;
        *(int4*)(sWhi + r * SROW_W + w16 * 4) = Whi4[r * 16 + w16];
        *(int4*)(sWlo + r * SROW_W + w16 * 4) = Wlo4[r * 16 + w16];
    }

    // ---- Phase 1: gather + pack split-bf16 rows into smem A ----
    const float4* __restrict__ hs4 = (const float4*)g_hs;
    const uint2* __restrict__ mh2 = (const uint2*)min_buf;
    for (int i = 0; i < 16; i++) {
        int r = warp * 16 + i;
        int v = row0 + r;
        float4 acc = make_float4(0.f, 0.f, 0.f, 0.f);
        float nd = 1.f;
        if (v < n) {
            int beg = g_ptr[v];
            int end = g_ptr[v + 1];
            int e = beg;
            if (mode_in == 0) {
                for (; e + 4 <= end; e += 4) {
                    int u0 = g_col[e + 0];
                    int u1 = g_col[e + 1];
                    int u2 = g_col[e + 2];
                    int u3 = g_col[e + 3];
                    float4 v0 = __ldg(hs4 + (size_t)u0 * 32 + lane);
                    float4 v1 = __ldg(hs4 + (size_t)u1 * 32 + lane);
                    float4 v2 = __ldg(hs4 + (size_t)u2 * 32 + lane);
                    float4 v3 = __ldg(hs4 + (size_t)u3 * 32 + lane);
                    acc.x += (v0.x + v1.x) + (v2.x + v3.x);
                    acc.y += (v0.y + v1.y) + (v2.y + v3.y);
                    acc.z += (v0.z + v1.z) + (v2.z + v3.z);
                    acc.w += (v0.w + v1.w) + (v2.w + v3.w);
                }
                for (; e < end; e++) {
                    int u = g_col[e];
                    float4 vv = __ldg(hs4 + (size_t)u * 32 + lane);
                    acc.x += vv.x;
                    acc.y += vv.y;
                    acc.z += vv.z;
                    acc.w += vv.w;
                }
            } else {
                for (; e + 4 <= end; e += 4) {
                    int u0 = g_col[e + 0];
                    int u1 = g_col[e + 1];
                    int u2 = g_col[e + 2];
                    int u3 = g_col[e + 3];
                    uint2 m0 = __ldg(mh2 + (size_t)u0 * 32 + lane);
                    uint2 m1 = __ldg(mh2 + (size_t)u1 * 32 + lane);
                    uint2 m2 = __ldg(mh2 + (size_t)u2 * 32 + lane);
                    uint2 m3 = __ldg(mh2 + (size_t)u3 * 32 + lane);
                    acc_h4(acc, m0);
                    acc_h4(acc, m1);
                    acc_h4(acc, m2);
                    acc_h4(acc, m3);
                }
                for (; e < end; e++) {
                    int u = g_col[e];
                    uint2 m = __ldg(mh2 + (size_t)u * 32 + lane);
                    acc_h4(acc, m);
                }
            }
            nd = g_norm_dst[v];
        }
        float o0 = acc.x * nd;
        float o1 = acc.y * nd;
        float o2 = acc.z * nd;
        float o3 = acc.w * nd;
        float l0;
        float l1;
        float l2;
        float l3;
        uint2 hi;
        uint2 lo;
        hi.x = pack2_hi_lo(o0, o1, l0, l1);
        hi.y = pack2_hi_lo(o2, o3, l2, l3);
        lo.x = pack2(l0, l1);
        lo.y = pack2(l2, l3);
        *(uint2*)(sAhi + r * SROW_A + 2 * lane) = hi;
        *(uint2*)(sAlo + r * SROW_A + 2 * lane) = lo;
    }
    __syncthreads();

    // ---- Phase 2: MMA. Warp grid 4(m) x 2(n); warp tile 32x64 = 2(mi) x 8(ni). ----
    int wm = warp >> 1;
    int wn = warp & 1;

    float c[2][8][4];
    #pragma unroll
    for (int mi = 0; mi < 2; mi++) {
        #pragma unroll
        for (int ni = 0; ni < 8; ni++) {
            #pragma unroll
            for (int r = 0; r < 4; r++) {
                c[mi][ni][r] = 0.f;
            }
        }
    }

    for (int kc = 0; kc < 2; kc++) {
        if (kc == 1) {
            __syncthreads();   // prior MMA reads of sW done
            #pragma unroll
            for (int j = 0; j < 4; j++) {
                int idx = tid + j * 256;
                int r = idx >> 3;
                int w16 = idx & 7;
                *(int4*)(sWhi + r * SROW_W + w16 * 4) = Whi4[r * 16 + 8 + w16];
                *(int4*)(sWlo + r * SROW_W + w16 * 4) = Wlo4[r * 16 + 8 + w16];
            }
            __syncthreads();
        }
        #pragma unroll
        for (int ks = 0; ks < 4; ks++) {
            unsigned int bh[16];
            unsigned int bl[16];
            #pragma unroll
            for (int ni = 0; ni < 8; ni++) {
                int boff = (wn * 64 + ni * 8 + (lane >> 2)) * SROW_W + ks * 8 + (lane & 3);
                bh[ni * 2 + 0] = sWhi[boff];
                bh[ni * 2 + 1] = sWhi[boff + 4];
                bl[ni * 2 + 0] = sWlo[boff];
                bl[ni * 2 + 1] = sWlo[boff + 4];
            }
            #pragma unroll
            for (int mi = 0; mi < 2; mi++) {
                int aoff = (wm * 32 + mi * 16 + (lane >> 2)) * SROW_A + kc * 32 + ks * 8 + (lane & 3);
                unsigned int ah[4];
                unsigned int al[4];
                ah[0] = sAhi[aoff];
                ah[1] = sAhi[aoff + 8 * SROW_A];
                ah[2] = sAhi[aoff + 4];
                ah[3] = sAhi[aoff + 8 * SROW_A + 4];
                al[0] = sAlo[aoff];
                al[1] = sAlo[aoff + 8 * SROW_A];
                al[2] = sAlo[aoff + 4];
                al[3] = sAlo[aoff + 8 * SROW_A + 4];
                #pragma unroll
                for (int ni = 0; ni < 8; ni++) {
                    mma_bf16(c[mi][ni], ah[0], ah[1], ah[2], ah[3], bh[ni * 2], bh[ni * 2 + 1]);
                    mma_bf16(c[mi][ni], ah[0], ah[1], ah[2], ah[3], bl[ni * 2], bl[ni * 2 + 1]);
                    mma_bf16(c[mi][ni], al[0], al[1], al[2], al[3], bh[ni * 2], bh[ni * 2 + 1]);
                }
            }
        }
    }

    // ---- epilogue ----
    #pragma unroll
    for (int mi = 0; mi < 2; mi++) {
        int r0 = row0 + wm * 32 + mi * 16 + (lane >> 2);
        int r1 = r0 + 8;
        #pragma unroll
        for (int ni = 0; ni < 8; ni++) {
            int col = wn * 64 + ni * 8 + (lane & 3) * 2;
            float2 bb = *(const float2*)(b + col);
            float y0 = fmaxf(c[mi][ni][0] + bb.x, 0.f);
            float y1 = fmaxf(c[mi][ni][1] + bb.y, 0.f);
            float y2 = fmaxf(c[mi][ni][2] + bb.x, 0.f);
            float y3 = fmaxf(c[mi][ni][3] + bb.y, 0.f);
            if (mode_out) {
                if (r0 < n) {
                    float ns = g_norm_src[r0];
                    __half2 v = __floats2half2_rn(y0 * ns, y1 * ns);
                    *reinterpret_cast<__half2*>(&mout_buf[(size_t)r0 * DD + col]) = v;
                }
                if (r1 < n) {
                    float ns = g_norm_src[r1];
                    __half2 v = __floats2half2_rn(y2 * ns, y3 * ns);
                    *reinterpret_cast<__half2*>(&mout_buf[(size_t)r1 * DD + col]) = v;
                }
            } else {
                if (r0 < n) {
                    float2 v;
                    v.x = y0;
                    v.y = y1;
                    *(float2*)&out[(size_t)r0 * DD + col] = v;
                }
                if (r1 < n) {
                    float2 v;
                    v.x = y2;
                    v.y = y3;
                    *(float2*)&out[(size_t)r1 * DD + col] = v;
                }
            }
        }
    }
}

// ---------------- launch ----------------
extern "C" void kernel_launch(void* const* d_in, const int* in_sizes, int n_in,
                              void* d_out, int out_size) {
    const int*   batch = (const int*)d_in[0];
    const int*   src   = (const int*)d_in[1];
    const int*   dst   = (const int*)d_in[2];
    const float* emb   = (const float*)d_in[3];
    const float* W1    = (const float*)d_in[4];
    const float* b1    = (const float*)d_in[5];
    const float* W2    = (const float*)d_in[6];
    const float* b2    = (const float*)d_in[7];
    const float* W3    = (const float*)d_in[8];
    const float* b3    = (const float*)d_in[9];
    float* out = (float*)d_out;

    int n = in_sizes[0];   // 50000
    int e = in_sizes[1];   // 800000

    int gb = (n + 255) / 256;   // 196 blocks
    int eb = (e + 255) / 256;

    static int smem_set = 0;
    if (!smem_set) {
        cudaFuncSetAttribute(k_layer, cudaFuncAttributeMaxDynamicSharedMemorySize, FUSED_SMEM);
        smem_set = 1;
    }

    // resolve device-global message buffer addresses (host-side, cached)
    static __half* mh0 = nullptr;
    static __half* mh1 = nullptr;
    if (!mh0) {
        cudaGetSymbolAddress((void**)&mh0, g_mh0);
        cudaGetSymbolAddress((void**)&mh1, g_mh1);
    }

    k_zero_degs<<<gb, 256>>>(n);
    k_count<<<eb, 256>>>(src, dst, e);
    k_norms_scan1<<<gb, 256>>>(n);
    k_scan_bsums<<<1, 256>>>(n, gb);
    k_add_off<<<gb, 256>>>(n);
    k_scatter<<<eb, 256>>>(src, dst, e);
    k_wprep<<<3 * 128, 128>>>(W1, W2, W3);
    k_embed<<<(n * 32 + 255) / 256, 256>>>(batch, emb, n);

    int layer_blocks = (n + 127) / 128;   // 391

    // ping-pong message buffers: no kernel reads and writes the same buffer
    k_layer<<<layer_blocks, 256, FUSED_SMEM>>>(0, b1, out, n, 0, 1, mh1, mh0);  // g_hs -> mh0
    k_layer<<<layer_blocks, 256, FUSED_SMEM>>>(1, b2, out, n, 1, 1, mh0, mh1);  // mh0  -> mh1
    k_layer<<<layer_blocks, 256, FUSED_SMEM>>>(2, b3, out, n, 1, 0, mh1, mh0);  // mh1  -> out
}

// round 10
// speedup vs baseline: 1.6186x; 1.6186x over previous
#include <cuda_runtime.h>
#include <cuda_bf16.h>
#include <cuda_fp16.h>
#include <cstdint>

// Problem constants (match reference)
#define NN 50000
#define EE 800000
#define DD 128

// ---------------- device scratch (no allocations allowed) ----------------
__device__ __half g_mh[NN * DD];                // h * norm_src (fp16 messages, all layers)
__device__ __nv_bfloat16 g_ahi[NN * DD];        // split-hi of aggregated messages
__device__ __nv_bfloat16 g_alo[NN * DD];        // split-lo of aggregated messages
__device__ __nv_bfloat16 g_wthi[3 * DD * DD];   // W^T split-hi, [layer][n][k]
__device__ __nv_bfloat16 g_wtlo[3 * DD * DD];   // W^T split-lo
__device__ float g_norm_src[NN];
__device__ float g_norm_dst[NN];
__device__ int   g_deg_out[NN];
__device__ int   g_deg_in[NN];
__device__ int   g_ptr[NN + 1];      // CSR row pointers (by dst)
__device__ int   g_cur[NN];          // scatter cursors
__device__ int   g_col[EE];          // CSR column indices (src node ids)
__device__ int   g_bsum[1024];       // per-block partial sums for scan

// ---------------- tiny setup kernels ----------------
__global__ void k_zero_degs(int n) {
    int i = blockIdx.x * blockDim.x + threadIdx.x;
    if (i < n) { g_deg_out[i] = 0; g_deg_in[i] = 0; }
}

__global__ void k_count(const int* __restrict__ src, const int* __restrict__ dst, int e) {
    int i = blockIdx.x * blockDim.x + threadIdx.x;
    if (i < e) {
        atomicAdd(&g_deg_out[src[i]], 1);
        atomicAdd(&g_deg_in[dst[i]], 1);
    }
}

// Fused: norms + per-block exclusive scan of deg_in (local) + block total.
__global__ void k_norms_scan1(int n) {
    __shared__ int wsum[8];
    int i = blockIdx.x * blockDim.x + threadIdx.x;
    int t = threadIdx.x;
    int lane = t & 31;
    int w = t >> 5;

    int din = 0;
    if (i < n) {
        int dout = g_deg_out[i];
        din = g_deg_in[i];
        g_norm_src[i] = rsqrtf((float)max(dout, 1));
        g_norm_dst[i] = rsqrtf((float)max(din, 1));
    }
    int v = din;
    #pragma unroll
    for (int off = 1; off < 32; off <<= 1) {
        int y = __shfl_up_sync(0xFFFFFFFFu, v, off);
        if (lane >= off) v += y;
    }
    if (lane == 31) wsum[w] = v;
    __syncthreads();
    if (t < 8) {
        int sv = wsum[t];
        #pragma unroll
        for (int off = 1; off < 8; off <<= 1) {
            int y = __shfl_up_sync(0xFFu, sv, off);
            if (t >= off) sv += y;
        }
        wsum[t] = sv;
    }
    __syncthreads();
    int warp_prefix = (w > 0) ? wsum[w - 1] : 0;
    int excl = v - din + warp_prefix;
    if (i < n) g_ptr[i] = excl;
    if (t == 255) g_bsum[blockIdx.x] = excl + din;
}

__global__ void k_scan_bsums(int n, int nb) {
    __shared__ int wsum[8];
    __shared__ int s_carry;
    int t = threadIdx.x;
    int lane = t & 31;
    int w = t >> 5;
    if (t == 0) s_carry = 0;
    __syncthreads();
    for (int base = 0; base < nb; base += 256) {
        int i = base + t;
        int x = (i < nb) ? g_bsum[i] : 0;
        int v = x;
        #pragma unroll
        for (int off = 1; off < 32; off <<= 1) {
            int y = __shfl_up_sync(0xFFFFFFFFu, v, off);
            if (lane >= off) v += y;
        }
        if (lane == 31) wsum[w] = v;
        __syncthreads();
        if (t < 8) {
            int sv = wsum[t];
            #pragma unroll
            for (int off = 1; off < 8; off <<= 1) {
                int y = __shfl_up_sync(0xFFu, sv, off);
                if (t >= off) sv += y;
            }
            wsum[t] = sv;
        }
        __syncthreads();
        int warp_prefix = (w > 0) ? wsum[w - 1] : 0;
        int incl = v + warp_prefix + s_carry;
        if (i < nb) g_bsum[i] = incl - x;
        __syncthreads();
        if (t == 255) s_carry = incl;
        __syncthreads();
    }
    if (t == 0) g_ptr[n] = s_carry;
}

__global__ void k_add_off(int n) {
    int i = blockIdx.x * blockDim.x + threadIdx.x;
    if (i < n) {
        int p = g_ptr[i] + g_bsum[blockIdx.x];
        g_ptr[i] = p;
        g_cur[i] = p;
    }
}

__global__ void k_scatter(const int* __restrict__ src, const int* __restrict__ dst, int e) {
    int i = blockIdx.x * blockDim.x + threadIdx.x;
    if (i < e) {
        int p = atomicAdd(&g_cur[dst[i]], 1);
        g_col[p] = src[i];
    }
}

// embedding gather + pre-scale by norm_src -> fp16 messages in g_mh
__global__ void k_embed(const int* __restrict__ batch, const float* __restrict__ emb, int n) {
    int i = blockIdx.x * blockDim.x + threadIdx.x;
    if (i < n * 32) {
        int v = i >> 5;
        int c = i & 31;
        int id = __ldg(&batch[v]);
        float4 val = __ldg(((const float4*)emb) + (size_t)id * 32 + c);
        float ns = g_norm_src[v];
        __half2 h0 = __floats2half2_rn(val.x * ns, val.y * ns);
        __half2 h1 = __floats2half2_rn(val.z * ns, val.w * ns);
        uint2 o;
        o.x = *reinterpret_cast<unsigned int*>(&h0);
        o.y = *reinterpret_cast<unsigned int*>(&h1);
        ((uint2*)g_mh)[(size_t)v * 32 + c] = o;
    }
}

// W^T split prep: 3*128 blocks of 128 thr: block = (layer, k); thread = n.
__global__ void k_wprep(const float* __restrict__ W1, const float* __restrict__ W2,
                        const float* __restrict__ W3) {
    int k = blockIdx.x & 127;
    int layer = blockIdx.x >> 7;
    const float* W = (layer == 0) ? W1 : (layer == 1) ? W2 : W3;
    int nn = threadIdx.x;
    float w = W[k * DD + nn];
    __nv_bfloat16 h = __float2bfloat16_rn(w);
    float l = w - __bfloat162float(h);
    g_wthi[layer * DD * DD + nn * DD + k] = h;
    g_wtlo[layer * DD * DD + nn * DD + k] = __float2bfloat16_rn(l);
}

// ---------------- SpMM epilogue helpers (split-bf16 pack) ----------------
__device__ __forceinline__ unsigned int pack2_hi_lo(float x, float y, float& lx, float& ly) {
    __nv_bfloat16 hx = __float2bfloat16_rn(x);
    __nv_bfloat16 hy = __float2bfloat16_rn(y);
    lx = x - __bfloat162float(hx);
    ly = y - __bfloat162float(hy);
    __nv_bfloat162 p = __halves2bfloat162(hx, hy);
    return *reinterpret_cast<unsigned int*>(&p);
}
__device__ __forceinline__ unsigned int pack2(float x, float y) {
    __nv_bfloat162 p = __floats2bfloat162_rn(x, y);
    return *reinterpret_cast<unsigned int*>(&p);
}

__device__ __forceinline__ void acc_h4(float4& acc, uint2 m) {
    __half2 p0 = *reinterpret_cast<__half2*>(&m.x);
    __half2 p1 = *reinterpret_cast<__half2*>(&m.y);
    float2 f0 = __half22float2(p0);
    float2 f1 = __half22float2(p1);
    acc.x += f0.x;
    acc.y += f0.y;
    acc.z += f1.x;
    acc.w += f1.y;
}

// ---------------- SpMM (pull mode, one warp per node, fp16 gather) ----------------
__global__ void k_spmm_h(int n) {
    int gw = (blockIdx.x * blockDim.x + threadIdx.x) >> 5;
    int lane = threadIdx.x & 31;
    if (gw >= n) return;
    int beg = g_ptr[gw];
    int end = g_ptr[gw + 1];
    const uint2* __restrict__ mh = (const uint2*)g_mh;   // 4 halves per lane
    float4 acc = make_float4(0.f, 0.f, 0.f, 0.f);
    int e = beg;
    for (; e + 4 <= end; e += 4) {
        int u0 = g_col[e + 0];
        int u1 = g_col[e + 1];
        int u2 = g_col[e + 2];
        int u3 = g_col[e + 3];
        uint2 m0 = __ldg(mh + (size_t)u0 * 32 + lane);
        uint2 m1 = __ldg(mh + (size_t)u1 * 32 + lane);
        uint2 m2 = __ldg(mh + (size_t)u2 * 32 + lane);
        uint2 m3 = __ldg(mh + (size_t)u3 * 32 + lane);
        acc_h4(acc, m0);
        acc_h4(acc, m1);
        acc_h4(acc, m2);
        acc_h4(acc, m3);
    }
    for (; e < end; e++) {
        int u = g_col[e];
        uint2 m = __ldg(mh + (size_t)u * 32 + lane);
        acc_h4(acc, m);
    }
    float nd = g_norm_dst[gw];
    float o0 = acc.x * nd;
    float o1 = acc.y * nd;
    float o2 = acc.z * nd;
    float o3 = acc.w * nd;
    float l0;
    float l1;
    float l2;
    float l3;
    uint2 hi;
    uint2 lo;
    hi.x = pack2_hi_lo(o0, o1, l0, l1);
    hi.y = pack2_hi_lo(o2, o3, l2, l3);
    lo.x = pack2(l0, l1);
    lo.y = pack2(l2, l3);
    ((uint2*)g_ahi)[(size_t)gw * 32 + lane] = hi;   // 4 bf16 per lane
    ((uint2*)g_alo)[(size_t)gw * 32 + lane] = lo;
}

// ---------------- tensor-core GEMM: out = relu(Aw + b), split-bf16 ----------------
// BM=128, BN=128 (full), K=128 in 2 chunks of 64. 256 threads = 8 warps.
// Warp grid 4(m) x 2(n): warp tile 32x64 = 2(mi) x 8(ni) mma m16n8k16 tiles.
// SMEM row stride: 72 bf16 = 36 words = 144B (16B-aligned rows, conflict-free frags).
#define SROW 36

__device__ __forceinline__ void mma_bf16(float* c,
                                         unsigned int a0, unsigned int a1,
                                         unsigned int a2, unsigned int a3,
                                         unsigned int b0, unsigned int b1) {
    asm volatile("mma.sync.aligned.m16n8k16.row.col.f32.bf16.bf16.f32 "
                 "{%0,%1,%2,%3}, {%4,%5,%6,%7}, {%8,%9}, {%0,%1,%2,%3};"
                 : "+f"(c[0]), "+f"(c[1]), "+f"(c[2]), "+f"(c[3])
                 : "r"(a0), "r"(a1), "r"(a2), "r"(a3), "r"(b0), "r"(b1));
}

// scale_out=1: write fp16 messages (y*norm_src) to g_mh. scale_out=0: fp32 to out.
// Safe aliasing: the SpMM before this kernel fully drained g_mh.
__global__ void __launch_bounds__(256, 2) k_gemm_mma(int layer, const float* __restrict__ b,
                                                     float* __restrict__ out, int n, int scale_out) {
    extern __shared__ unsigned int sm[];
    unsigned int* sAhi = sm;                      // 128 * 36 words = 18KB each
    unsigned int* sAlo = sm + 128 * SROW;
    unsigned int* sWhi = sm + 2 * 128 * SROW;
    unsigned int* sWlo = sm + 3 * 128 * SROW;

    int tid = threadIdx.x;
    int lane = tid & 31;
    int warp = tid >> 5;
    int wm = warp >> 1;
    int wn = warp & 1;
    int row0 = blockIdx.x * 128;

    float c[2][8][4];
    #pragma unroll
    for (int mi = 0; mi < 2; mi++) {
        #pragma unroll
        for (int ni = 0; ni < 8; ni++) {
            #pragma unroll
            for (int r = 0; r < 4; r++) {
                c[mi][ni][r] = 0.f;
            }
        }
    }

    const int4* Ahi4 = (const int4*)g_ahi;
    const int4* Alo4 = (const int4*)g_alo;
    const int4* Whi4 = (const int4*)(g_wthi + layer * DD * DD);
    const int4* Wlo4 = (const int4*)(g_wtlo + layer * DD * DD);

    for (int kc = 0; kc < 2; kc++) {
        // load A/W chunks: rows 0..127, k in [kc*64, kc*64+64) = 8 int4 per row
        #pragma unroll
        for (int j = 0; j < 4; j++) {
            int idx = tid + j * 256;
            int r = idx >> 3;
            int w16 = idx & 7;
            int4 vh = make_int4(0, 0, 0, 0);
            int4 vl = make_int4(0, 0, 0, 0);
            if (row0 + r < n) {
                vh = Ahi4[(size_t)(row0 + r) * 16 + kc * 8 + w16];
                vl = Alo4[(size_t)(row0 + r) * 16 + kc * 8 + w16];
            }
            *(int4*)(sAhi + r * SROW + w16 * 4) = vh;
            *(int4*)(sAlo + r * SROW + w16 * 4) = vl;
            *(int4*)(sWhi + r * SROW + w16 * 4) = Whi4[r * 16 + kc * 8 + w16];
            *(int4*)(sWlo + r * SROW + w16 * 4) = Wlo4[r * 16 + kc * 8 + w16];
        }
        __syncthreads();
        #pragma unroll
        for (int ks = 0; ks < 4; ks++) {
            unsigned int bh[16];
            unsigned int bl[16];
            #pragma unroll
            for (int ni = 0; ni < 8; ni++) {
                int boff = (wn * 64 + ni * 8 + (lane >> 2)) * SROW + ks * 8 + (lane & 3);
                bh[ni * 2 + 0] = sWhi[boff];
                bh[ni * 2 + 1] = sWhi[boff + 4];
                bl[ni * 2 + 0] = sWlo[boff];
                bl[ni * 2 + 1] = sWlo[boff + 4];
            }
            #pragma unroll
            for (int mi = 0; mi < 2; mi++) {
                int aoff = (wm * 32 + mi * 16 + (lane >> 2)) * SROW + ks * 8 + (lane & 3);
                unsigned int ah[4];
                unsigned int al[4];
                ah[0] = sAhi[aoff];
                ah[1] = sAhi[aoff + 8 * SROW];
                ah[2] = sAhi[aoff + 4];
                ah[3] = sAhi[aoff + 8 * SROW + 4];
                al[0] = sAlo[aoff];
                al[1] = sAlo[aoff + 8 * SROW];
                al[2] = sAlo[aoff + 4];
                al[3] = sAlo[aoff + 8 * SROW + 4];
                #pragma unroll
                for (int ni = 0; ni < 8; ni++) {
                    mma_bf16(c[mi][ni], ah[0], ah[1], ah[2], ah[3], bh[ni * 2], bh[ni * 2 + 1]);
                    mma_bf16(c[mi][ni], ah[0], ah[1], ah[2], ah[3], bl[ni * 2], bl[ni * 2 + 1]);
                    mma_bf16(c[mi][ni], al[0], al[1], al[2], al[3], bh[ni * 2], bh[ni * 2 + 1]);
                }
            }
        }
        __syncthreads();
    }

    // epilogue
    #pragma unroll
    for (int mi = 0; mi < 2; mi++) {
        int r0 = row0 + wm * 32 + mi * 16 + (lane >> 2);
        int r1 = r0 + 8;
        #pragma unroll
        for (int ni = 0; ni < 8; ni++) {
            int col = wn * 64 + ni * 8 + (lane & 3) * 2;
            float2 bb = *(const float2*)(b + col);
            float y0 = fmaxf(c[mi][ni][0] + bb.x, 0.f);
            float y1 = fmaxf(c[mi][ni][1] + bb.y, 0.f);
            float y2 = fmaxf(c[mi][ni][2] + bb.x, 0.f);
            float y3 = fmaxf(c[mi][ni][3] + bb.y, 0.f);
            if (scale_out) {
                if (r0 < n) {
                    float ns = g_norm_src[r0];
                    __half2 v = __floats2half2_rn(y0 * ns, y1 * ns);
                    *reinterpret_cast<__half2*>(&g_mh[(size_t)r0 * DD + col]) = v;
                }
                if (r1 < n) {
                    float ns = g_norm_src[r1];
                    __half2 v = __floats2half2_rn(y2 * ns, y3 * ns);
                    *reinterpret_cast<__half2*>(&g_mh[(size_t)r1 * DD + col]) = v;
                }
            } else {
                if (r0 < n) {
                    float2 v;
                    v.x = y0;
                    v.y = y1;
                    *(float2*)&out[(size_t)r0 * DD + col] = v;
                }
                if (r1 < n) {
                    float2 v;
                    v.x = y2;
                    v.y = y3;
                    *(float2*)&out[(size_t)r1 * DD + col] = v;
                }
            }
        }
    }
}

// ---------------- launch ----------------
extern "C" void kernel_launch(void* const* d_in, const int* in_sizes, int n_in,
                              void* d_out, int out_size) {
    const int*   batch = (const int*)d_in[0];
    const int*   src   = (const int*)d_in[1];
    const int*   dst   = (const int*)d_in[2];
    const float* emb   = (const float*)d_in[3];
    const float* W1    = (const float*)d_in[4];
    const float* b1    = (const float*)d_in[5];
    const float* W2    = (const float*)d_in[6];
    const float* b2    = (const float*)d_in[7];
    const float* W3    = (const float*)d_in[8];
    const float* b3    = (const float*)d_in[9];
    float* out = (float*)d_out;

    int n = in_sizes[0];   // 50000
    int e = in_sizes[1];   // 800000

    int gb = (n + 255) / 256;   // 196 blocks
    int eb = (e + 255) / 256;

    static int smem_set = 0;
    const int GEMM_SMEM = 4 * 128 * SROW * 4;   // 73728 bytes
    if (!smem_set) {
        cudaFuncSetAttribute(k_gemm_mma, cudaFuncAttributeMaxDynamicSharedMemorySize, GEMM_SMEM);
        smem_set = 1;
    }

    k_zero_degs<<<gb, 256>>>(n);
    k_count<<<eb, 256>>>(src, dst, e);
    k_norms_scan1<<<gb, 256>>>(n);
    k_scan_bsums<<<1, 256>>>(n, gb);
    k_add_off<<<gb, 256>>>(n);
    k_scatter<<<eb, 256>>>(src, dst, e);
    k_wprep<<<3 * 128, 128>>>(W1, W2, W3);
    k_embed<<<(n * 32 + 255) / 256, 256>>>(batch, emb, n);

    int spmm_blocks = (n + 7) / 8;
    int gemm_blocks = (n + 127) / 128;

    k_spmm_h<<<spmm_blocks, 256>>>(n);                               // fp16 gather
    k_gemm_mma<<<gemm_blocks, 256, GEMM_SMEM>>>(0, b1, out, n, 1);   // -> fp16 messages

    k_spmm_h<<<spmm_blocks, 256>>>(n);
    k_gemm_mma<<<gemm_blocks, 256, GEMM_SMEM>>>(1, b2, out, n, 1);

    k_spmm_h<<<spmm_blocks, 256>>>(n);
    k_gemm_mma<<<gemm_blocks, 256, GEMM_SMEM>>>(2, b3, out, n, 0);   // -> fp32 out
}

// round 13
// speedup vs baseline: 1.8821x; 1.1628x over previous
#include <cuda_runtime.h>
#include <cuda_bf16.h>
#include <cuda_fp16.h>
#include <cstdint>

// Problem constants (match reference)
#define NN 50000
#define EE 800000
#define DD 128

// ---------------- device scratch (no allocations allowed) ----------------
__device__ __half g_mh[NN * DD];      // h * norm_src (fp16 messages, all layers)
__device__ __half g_agg[NN * DD];     // aggregated messages (fp16, GEMM A input)
__device__ __half g_wthi[3 * DD * DD];   // W^T split-hi (fp16), [layer][n][k]
__device__ __half g_wtlo[3 * DD * DD];   // W^T split-lo (fp16)
__device__ float g_norm_src[NN];
__device__ float g_norm_dst[NN];
__device__ int   g_deg_out[NN];
__device__ int   g_deg_in[NN];
__device__ int   g_ptr[NN + 1];      // CSR row pointers (by dst)
__device__ int   g_cur[NN];          // scatter cursors
__device__ int   g_col[EE];          // CSR column indices (src node ids)
__device__ int   g_bsum[1024];       // per-block partial sums for scan

// ---------------- tiny setup kernels ----------------
__global__ void k_zero_degs(int n) {
    int i = blockIdx.x * blockDim.x + threadIdx.x;
    if (i < n) { g_deg_out[i] = 0; g_deg_in[i] = 0; }
}

__global__ void k_count(const int* __restrict__ src, const int* __restrict__ dst, int e) {
    int i = blockIdx.x * blockDim.x + threadIdx.x;
    if (i < e) {
        atomicAdd(&g_deg_out[src[i]], 1);
        atomicAdd(&g_deg_in[dst[i]], 1);
    }
}

// Fused: norms + per-block exclusive scan of deg_in (local) + block total.
__global__ void k_norms_scan1(int n) {
    __shared__ int wsum[8];
    int i = blockIdx.x * blockDim.x + threadIdx.x;
    int t = threadIdx.x;
    int lane = t & 31;
    int w = t >> 5;

    int din = 0;
    if (i < n) {
        int dout = g_deg_out[i];
        din = g_deg_in[i];
        g_norm_src[i] = rsqrtf((float)max(dout, 1));
        g_norm_dst[i] = rsqrtf((float)max(din, 1));
    }
    int v = din;
    #pragma unroll
    for (int off = 1; off < 32; off <<= 1) {
        int y = __shfl_up_sync(0xFFFFFFFFu, v, off);
        if (lane >= off) v += y;
    }
    if (lane == 31) wsum[w] = v;
    __syncthreads();
    if (t < 8) {
        int sv = wsum[t];
        #pragma unroll
        for (int off = 1; off < 8; off <<= 1) {
            int y = __shfl_up_sync(0xFFu, sv, off);
            if (t >= off) sv += y;
        }
        wsum[t] = sv;
    }
    __syncthreads();
    int warp_prefix = (w > 0) ? wsum[w - 1] : 0;
    int excl = v - din + warp_prefix;
    if (i < n) g_ptr[i] = excl;
    if (t == 255) g_bsum[blockIdx.x] = excl + din;
}

__global__ void k_scan_bsums(int n, int nb) {
    __shared__ int wsum[8];
    __shared__ int s_carry;
    int t = threadIdx.x;
    int lane = t & 31;
    int w = t >> 5;
    if (t == 0) s_carry = 0;
    __syncthreads();
    for (int base = 0; base < nb; base += 256) {
        int i = base + t;
        int x = (i < nb) ? g_bsum[i] : 0;
        int v = x;
        #pragma unroll
        for (int off = 1; off < 32; off <<= 1) {
            int y = __shfl_up_sync(0xFFFFFFFFu, v, off);
            if (lane >= off) v += y;
        }
        if (lane == 31) wsum[w] = v;
        __syncthreads();
        if (t < 8) {
            int sv = wsum[t];
            #pragma unroll
            for (int off = 1; off < 8; off <<= 1) {
                int y = __shfl_up_sync(0xFFu, sv, off);
                if (t >= off) sv += y;
            }
            wsum[t] = sv;
        }
        __syncthreads();
        int warp_prefix = (w > 0) ? wsum[w - 1] : 0;
        int incl = v + warp_prefix + s_carry;
        if (i < nb) g_bsum[i] = incl - x;
        __syncthreads();
        if (t == 255) s_carry = incl;
        __syncthreads();
    }
    if (t == 0) g_ptr[n] = s_carry;
}

__global__ void k_add_off(int n) {
    int i = blockIdx.x * blockDim.x + threadIdx.x;
    if (i < n) {
        int p = g_ptr[i] + g_bsum[blockIdx.x];
        g_ptr[i] = p;
        g_cur[i] = p;
    }
}

__global__ void k_scatter(const int* __restrict__ src, const int* __restrict__ dst, int e) {
    int i = blockIdx.x * blockDim.x + threadIdx.x;
    if (i < e) {
        int p = atomicAdd(&g_cur[dst[i]], 1);
        g_col[p] = src[i];
    }
}

// embedding gather + pre-scale by norm_src -> fp16 messages in g_mh
__global__ void k_embed(const int* __restrict__ batch, const float* __restrict__ emb, int n) {
    int i = blockIdx.x * blockDim.x + threadIdx.x;
    if (i < n * 32) {
        int v = i >> 5;
        int c = i & 31;
        int id = __ldg(&batch[v]);
        float4 val = __ldg(((const float4*)emb) + (size_t)id * 32 + c);
        float ns = g_norm_src[v];
        __half2 h0 = __floats2half2_rn(val.x * ns, val.y * ns);
        __half2 h1 = __floats2half2_rn(val.z * ns, val.w * ns);
        uint2 o;
        o.x = *reinterpret_cast<unsigned int*>(&h0);
        o.y = *reinterpret_cast<unsigned int*>(&h1);
        ((uint2*)g_mh)[(size_t)v * 32 + c] = o;
    }
}

// W^T split prep (fp16 hi/lo): 3*128 blocks of 128 thr: block = (layer, k); thread = n.
__global__ void k_wprep(const float* __restrict__ W1, const float* __restrict__ W2,
                        const float* __restrict__ W3) {
    int k = blockIdx.x & 127;
    int layer = blockIdx.x >> 7;
    const float* W = (layer == 0) ? W1 : (layer == 1) ? W2 : W3;
    int nn = threadIdx.x;
    float w = W[k * DD + nn];
    __half h = __float2half_rn(w);
    float l = w - __half2float(h);
    g_wthi[layer * DD * DD + nn * DD + k] = h;
    g_wtlo[layer * DD * DD + nn * DD + k] = __float2half_rn(l);
}

// ---------------- SpMM helpers ----------------
__device__ __forceinline__ void acc_h4(float4& acc, uint2 m) {
    __half2 p0 = *reinterpret_cast<__half2*>(&m.x);
    __half2 p1 = *reinterpret_cast<__half2*>(&m.y);
    float2 f0 = __half22float2(p0);
    float2 f1 = __half22float2(p1);
    acc.x += f0.x;
    acc.y += f0.y;
    acc.z += f1.x;
    acc.w += f1.y;
}

// ---------------- SpMM (pull mode, one warp per node, fp16 gather -> fp16 agg) ----------------
__global__ void k_spmm_h(int n) {
    int gw = (blockIdx.x * blockDim.x + threadIdx.x) >> 5;
    int lane = threadIdx.x & 31;
    if (gw >= n) return;
    int beg = g_ptr[gw];
    int end = g_ptr[gw + 1];
    const uint2* __restrict__ mh = (const uint2*)g_mh;   // 4 halves per lane
    float4 acc = make_float4(0.f, 0.f, 0.f, 0.f);
    int e = beg;
    for (; e + 4 <= end; e += 4) {
        int u0 = g_col[e + 0];
        int u1 = g_col[e + 1];
        int u2 = g_col[e + 2];
        int u3 = g_col[e + 3];
        uint2 m0 = __ldg(mh + (size_t)u0 * 32 + lane);
        uint2 m1 = __ldg(mh + (size_t)u1 * 32 + lane);
        uint2 m2 = __ldg(mh + (size_t)u2 * 32 + lane);
        uint2 m3 = __ldg(mh + (size_t)u3 * 32 + lane);
        acc_h4(acc, m0);
        acc_h4(acc, m1);
        acc_h4(acc, m2);
        acc_h4(acc, m3);
    }
    for (; e < end; e++) {
        int u = g_col[e];
        uint2 m = __ldg(mh + (size_t)u * 32 + lane);
        acc_h4(acc, m);
    }
    float nd = g_norm_dst[gw];
    __half2 h0 = __floats2half2_rn(acc.x * nd, acc.y * nd);
    __half2 h1 = __floats2half2_rn(acc.z * nd, acc.w * nd);
    uint2 o;
    o.x = *reinterpret_cast<unsigned int*>(&h0);
    o.y = *reinterpret_cast<unsigned int*>(&h1);
    ((uint2*)g_agg)[(size_t)gw * 32 + lane] = o;   // 4 fp16 per lane
}

// ---------------- tensor-core GEMM: out = relu(Aw + b), fp16 A + fp16-split W ----------------
// BM=128, BN=128 (full), K=128 in 2 chunks of 64. 256 threads = 8 warps.
// Warp grid 4(m) x 2(n): warp tile 32x64 = 2(mi) x 8(ni) mma m16n8k16 tiles, 2 MMAs each.
// SMEM row stride 36 words (32 data + 4 pad) for A, Whi, Wlo chunks.
#define SROW 36

__device__ __forceinline__ void mma_f16(float* c,
                                        unsigned int a0, unsigned int a1,
                                        unsigned int a2, unsigned int a3,
                                        unsigned int b0, unsigned int b1) {
    asm volatile("mma.sync.aligned.m16n8k16.row.col.f32.f16.f16.f32 "
                 "{%0,%1,%2,%3}, {%4,%5,%6,%7}, {%8,%9}, {%0,%1,%2,%3};"
                 : "+f"(c[0]), "+f"(c[1]), "+f"(c[2]), "+f"(c[3])
                 : "r"(a0), "r"(a1), "r"(a2), "r"(a3), "r"(b0), "r"(b1));
}

// scale_out=1: write fp16 messages (y*norm_src) to g_mh. scale_out=0: fp32 to out.
// Safe aliasing: the SpMM before this kernel fully drained g_mh into g_agg.
__global__ void __launch_bounds__(256, 2) k_gemm_mma(int layer, const float* __restrict__ b,
                                                     float* __restrict__ out, int n, int scale_out) {
    extern __shared__ unsigned int sm[];
    unsigned int* sA   = sm;                      // 128 * 36 words = 18KB each
    unsigned int* sWhi = sm + 128 * SROW;
    unsigned int* sWlo = sm + 2 * 128 * SROW;

    int tid = threadIdx.x;
    int lane = tid & 31;
    int warp = tid >> 5;
    int wm = warp >> 1;
    int wn = warp & 1;
    int row0 = blockIdx.x * 128;

    float c[2][8][4];
    #pragma unroll
    for (int mi = 0; mi < 2; mi++) {
        #pragma unroll
        for (int ni = 0; ni < 8; ni++) {
            #pragma unroll
            for (int r = 0; r < 4; r++) {
                c[mi][ni][r] = 0.f;
            }
        }
    }

    const int4* A4   = (const int4*)g_agg;                        // row = 16 int4
    const int4* Whi4 = (const int4*)(g_wthi + layer * DD * DD);   // row = 16 int4
    const int4* Wlo4 = (const int4*)(g_wtlo + layer * DD * DD);

    for (int kc = 0; kc < 2; kc++) {
        // load A/W chunks: rows 0..127, k in [kc*64, kc*64+64) = 8 int4 per row
        #pragma unroll
        for (int j = 0; j < 4; j++) {
            int idx = tid + j * 256;
            int r = idx >> 3;
            int w16 = idx & 7;
            int4 va = make_int4(0, 0, 0, 0);
            if (row0 + r < n) {
                va = A4[(size_t)(row0 + r) * 16 + kc * 8 + w16];
            }
            *(int4*)(sA + r * SROW + w16 * 4) = va;
            *(int4*)(sWhi + r * SROW + w16 * 4) = Whi4[r * 16 + kc * 8 + w16];
            *(int4*)(sWlo + r * SROW + w16 * 4) = Wlo4[r * 16 + kc * 8 + w16];
        }
        __syncthreads();
        #pragma unroll
        for (int ks = 0; ks < 4; ks++) {
            unsigned int bh[16];
            unsigned int bl[16];
            #pragma unroll
            for (int ni = 0; ni < 8; ni++) {
                int boff = (wn * 64 + ni * 8 + (lane >> 2)) * SROW + ks * 8 + (lane & 3);
                bh[ni * 2 + 0] = sWhi[boff];
                bh[ni * 2 + 1] = sWhi[boff + 4];
                bl[ni * 2 + 0] = sWlo[boff];
                bl[ni * 2 + 1] = sWlo[boff + 4];
            }
            #pragma unroll
            for (int mi = 0; mi < 2; mi++) {
                int aoff = (wm * 32 + mi * 16 + (lane >> 2)) * SROW + ks * 8 + (lane & 3);
                unsigned int ah[4];
                ah[0] = sA[aoff];
                ah[1] = sA[aoff + 8 * SROW];
                ah[2] = sA[aoff + 4];
                ah[3] = sA[aoff + 8 * SROW + 4];
                #pragma unroll
                for (int ni = 0; ni < 8; ni++) {
                    mma_f16(c[mi][ni], ah[0], ah[1], ah[2], ah[3], bh[ni * 2], bh[ni * 2 + 1]);
                    mma_f16(c[mi][ni], ah[0], ah[1], ah[2], ah[3], bl[ni * 2], bl[ni * 2 + 1]);
                }
            }
        }
        __syncthreads();
    }

    // epilogue
    #pragma unroll
    for (int mi = 0; mi < 2; mi++) {
        int r0 = row0 + wm * 32 + mi * 16 + (lane >> 2);
        int r1 = r0 + 8;
        #pragma unroll
        for (int ni = 0; ni < 8; ni++) {
            int col = wn * 64 + ni * 8 + (lane & 3) * 2;
            float2 bb = *(const float2*)(b + col);
            float y0 = fmaxf(c[mi][ni][0] + bb.x, 0.f);
            float y1 = fmaxf(c[mi][ni][1] + bb.y, 0.f);
            float y2 = fmaxf(c[mi][ni][2] + bb.x, 0.f);
            float y3 = fmaxf(c[mi][ni][3] + bb.y, 0.f);
            if (scale_out) {
                if (r0 < n) {
                    float ns = g_norm_src[r0];
                    __half2 v = __floats2half2_rn(y0 * ns, y1 * ns);
                    *reinterpret_cast<__half2*>(&g_mh[(size_t)r0 * DD + col]) = v;
                }
                if (r1 < n) {
                    float ns = g_norm_src[r1];
                    __half2 v = __floats2half2_rn(y2 * ns, y3 * ns);
                    *reinterpret_cast<__half2*>(&g_mh[(size_t)r1 * DD + col]) = v;
                }
            } else {
                if (r0 < n) {
                    float2 v;
                    v.x = y0;
                    v.y = y1;
                    *(float2*)&out[(size_t)r0 * DD + col] = v;
                }
                if (r1 < n) {
                    float2 v;
                    v.x = y2;
                    v.y = y3;
                    *(float2*)&out[(size_t)r1 * DD + col] = v;
                }
            }
        }
    }
}

// ---------------- launch ----------------
extern "C" void kernel_launch(void* const* d_in, const int* in_sizes, int n_in,
                              void* d_out, int out_size) {
    const int*   batch = (const int*)d_in[0];
    const int*   src   = (const int*)d_in[1];
    const int*   dst   = (const int*)d_in[2];
    const float* emb   = (const float*)d_in[3];
    const float* W1    = (const float*)d_in[4];
    const float* b1    = (const float*)d_in[5];
    const float* W2    = (const float*)d_in[6];
    const float* b2    = (const float*)d_in[7];
    const float* W3    = (const float*)d_in[8];
    const float* b3    = (const float*)d_in[9];
    float* out = (float*)d_out;

    int n = in_sizes[0];   // 50000
    int e = in_sizes[1];   // 800000

    int gb = (n + 255) / 256;   // 196 blocks
    int eb = (e + 255) / 256;

    static int smem_set = 0;
    const int GEMM_SMEM = 3 * 128 * SROW * 4;   // 55296 bytes
    if (!smem_set) {
        cudaFuncSetAttribute(k_gemm_mma, cudaFuncAttributeMaxDynamicSharedMemorySize, GEMM_SMEM);
        smem_set = 1;
    }

    k_zero_degs<<<gb, 256>>>(n);
    k_count<<<eb, 256>>>(src, dst, e);
    k_norms_scan1<<<gb, 256>>>(n);
    k_scan_bsums<<<1, 256>>>(n, gb);
    k_add_off<<<gb, 256>>>(n);
    k_scatter<<<eb, 256>>>(src, dst, e);
    k_wprep<<<3 * 128, 128>>>(W1, W2, W3);
    k_embed<<<(n * 32 + 255) / 256, 256>>>(batch, emb, n);

    int spmm_blocks = (n + 7) / 8;
    int gemm_blocks = (n + 127) / 128;

    k_spmm_h<<<spmm_blocks, 256>>>(n);                               // fp16 gather -> fp16 agg
    k_gemm_mma<<<gemm_blocks, 256, GEMM_SMEM>>>(0, b1, out, n, 1);   // -> fp16 messages

    k_spmm_h<<<spmm_blocks, 256>>>(n);
    k_gemm_mma<<<gemm_blocks, 256, GEMM_SMEM>>>(1, b2, out, n, 1);

    k_spmm_h<<<spmm_blocks, 256>>>(n);
    k_gemm_mma<<<gemm_blocks, 256, GEMM_SMEM>>>(2, b3, out, n, 0);   // -> fp32 out
}